// round 17
// baseline (speedup 1.0000x reference)
#include <cuda_runtime.h>
#include <cuda_fp16.h>
#include <cstdint>

#define NN    50000
#define EE    800000
#define FIN   256
#define FOUT  96
#define NF    3
#define FT    (NF * FOUT)    // 288
#define EPS   0.1f
#define CAP   64             // bucket capacity per row (max degree ~45)

// Scratch (allocation-free rule: __device__ globals)
__device__ __align__(128) __half g_Th[(size_t)NN * FT];   // 28.8 MB
__device__ __align__(128) __half g_Wt[NF * FOUT * FIN];   // W^T fp16 [f][n][k]
__device__ int  g_cnt[NN];
__device__ __align__(16) int2 g_csrb[(size_t)NN * CAP];   // 25.6 MB buckets

// ---------------------------------------------------------------------------
// Bucketed CSR build (R10 verbatim)
// ---------------------------------------------------------------------------
__global__ void k_cnt0() {
    int i = blockIdx.x * blockDim.x + threadIdx.x;
    if (i < NN) g_cnt[i] = 0;
}

__global__ void k_bucket(const int* __restrict__ ei,
                         const float* __restrict__ adj) {
    int e = blockIdx.x * blockDim.x + threadIdx.x;
    if (e < EE) {
        int r = ei[e];
        int pos = atomicAdd(&g_cnt[r], 1);
        if (pos < CAP) {
            int2 pay;
            pay.x = ei[EE + e];
            pay.y = __float_as_int(adj[e]);
            g_csrb[(size_t)r * CAP + pos] = pay;
        }
    }
}

// ---------------------------------------------------------------------------
// W -> fp16 transposed [f][n][k]  (runs on main stream right before gemm)
// ---------------------------------------------------------------------------
__global__ void k_wcvt(const float* __restrict__ w) {
    int i = blockIdx.x * blockDim.x + threadIdx.x;
    if (i < NF * FIN * FOUT) {
        int f = i / (FIN * FOUT);
        int rem = i - f * FIN * FOUT;
        int k = rem / FOUT;
        int n = rem - k * FOUT;
        g_Wt[(size_t)f * FOUT * FIN + (size_t)n * FIN + k] = __float2half(w[i]);
    }
}

// ---------------------------------------------------------------------------
// fp16 GEMM with FUSED x fp32->fp16 conversion on the A-path.
// T[n][f*96+c] = ds[f][n] * (x @ W_f)[n][c]
// BM=128, BN=96 (blockIdx.y = filter), BK=32, 8 stages, 256 threads.
// 3-buffer circular pipeline, ONE __syncthreads per stage:
//   iteration it: read buf(it%3); STS A(it+1) -> buf((it+1)%3);
//   cp.async B(it+2) -> buf((it+2)%3).  All distinct mod 3.
// ---------------------------------------------------------------------------
#define A_STR 40
#define B_STR 40
#define STAGE_H (128 * A_STR + 96 * B_STR)   // 8960 halves per stage
#define GEMM_SMEM (3 * STAGE_H * 2)          // 53760 B
#define NSTG 8                               // K = 8 * 32

__device__ __forceinline__ void cpa16h(__half* smem, const __half* g) {
    uint32_t s = (uint32_t)__cvta_generic_to_shared(smem);
    asm volatile("cp.async.ca.shared.global [%0], [%1], 16;"
                 :: "r"(s), "l"(g));
}

__device__ __forceinline__ void mma16(float* c, const uint32_t* a,
                                      uint32_t b0, uint32_t b1) {
    asm volatile(
        "mma.sync.aligned.m16n8k16.row.col.f32.f16.f16.f32 "
        "{%0,%1,%2,%3}, {%4,%5,%6,%7}, {%8,%9}, {%0,%1,%2,%3};"
        : "+f"(c[0]), "+f"(c[1]), "+f"(c[2]), "+f"(c[3])
        : "r"(a[0]), "r"(a[1]), "r"(a[2]), "r"(a[3]), "r"(b0), "r"(b1));
}

__device__ __forceinline__ void ldsm4(uint32_t* r, uint32_t addr) {
    asm volatile("ldmatrix.sync.aligned.m8n8.x4.shared.b16 {%0,%1,%2,%3}, [%4];"
                 : "=r"(r[0]), "=r"(r[1]), "=r"(r[2]), "=r"(r[3]) : "r"(addr));
}

__global__ __launch_bounds__(256, 2) void k_gemm(const float* __restrict__ ds,
                                                 const float* __restrict__ x) {
    extern __shared__ __half sm[];

    const int m0 = blockIdx.x * 128;
    const int f  = blockIdx.y;
    const __half* Wt = g_Wt + (size_t)f * FOUT * FIN;

    const int tid  = threadIdx.x;
    const int wid  = tid >> 5;
    const int lane = tid & 31;
    const int g    = lane >> 2;
    const int t4   = lane & 3;
    const int mw   = (wid & 3) * 32;
    const int nw   = (wid >> 2) * 48;

    const int aRow = lane & 15;
    const int aCol = (lane >> 4) << 3;
    const int bRow = ((lane >> 4) << 3) + (lane & 7);
    const int bCol = ((lane >> 3) & 1) << 3;

    // A-load geometry: 128 rows x 8 float4-chunks = 1024 tasks, 4/thread
    int am[4], aq[4];
    bool aok[4];
    #pragma unroll
    for (int i = 0; i < 4; i++) {
        int idx = tid + i * 256;
        am[i] = idx >> 3;
        aq[i] = (idx & 7) * 4;
        aok[i] = (m0 + am[i]) < NN;
    }

    float c[2][6][4];
    #pragma unroll
    for (int mt = 0; mt < 2; mt++)
        #pragma unroll
        for (int nt = 0; nt < 6; nt++)
            #pragma unroll
            for (int q = 0; q < 4; q++) c[mt][nt][q] = 0.0f;

    float4 areg[4];
    auto loadA = [&](int s) {
        #pragma unroll
        for (int i = 0; i < 4; i++)
            areg[i] = aok[i]
                ? *(const float4*)(x + (size_t)(m0 + am[i]) * FIN + s * 32 + aq[i])
                : make_float4(0.f, 0.f, 0.f, 0.f);
    };
    auto stsA = [&](int s) {
        __half* As = sm + (s % 3) * STAGE_H;
        #pragma unroll
        for (int i = 0; i < 4; i++) {
            __half2 lo = __floats2half2_rn(areg[i].x, areg[i].y);
            __half2 hi = __floats2half2_rn(areg[i].z, areg[i].w);
            uint2 p;
            p.x = *(uint32_t*)&lo;
            p.y = *(uint32_t*)&hi;
            *(uint2*)(As + am[i] * A_STR + aq[i]) = p;
        }
    };
    auto fetchB = [&](int s) {
        __half* Bs = sm + (s % 3) * STAGE_H + 128 * A_STR;
        #pragma unroll
        for (int i = 0; i < 2; i++) {
            int idx = tid + i * 256;
            if (idx < 384) {               // 96 rows x 4 chunks of 8 halves
                int n  = idx >> 2;
                int kg = (idx & 3) * 8;
                cpa16h(Bs + n * B_STR + kg, Wt + (size_t)n * FIN + s * 32 + kg);
            }
        }
        asm volatile("cp.async.commit_group;");
    };

    // prologue: A(0) in smem, A(1) in regs, B(0) and B(1) committed
    loadA(0); stsA(0);
    loadA(1);
    fetchB(0);
    fetchB(1);

    #pragma unroll
    for (int it = 0; it < NSTG; it++) {
        if (it == NSTG - 1) asm volatile("cp.async.wait_group 0;");
        else                asm volatile("cp.async.wait_group 1;");
        __syncthreads();    // single barrier per stage

        // STS next A tile (buf (it+1)%3) and issue next-next loads; the
        // LDG latency is hidden under this stage's MMAs.
        if (it + 1 < NSTG) stsA(it + 1);
        if (it + 2 < NSTG) loadA(it + 2);

        const __half* As = sm + (it % 3) * STAGE_H;
        const __half* Bs = As + 128 * A_STR;

        uint32_t aAddr[2];
        #pragma unroll
        for (int mt = 0; mt < 2; mt++) {
            int mb = mw + mt * 16;
            aAddr[mt] = (uint32_t)__cvta_generic_to_shared(
                As + (mb + aRow) * A_STR + aCol);
        }
        uint32_t bAddr[3];
        #pragma unroll
        for (int p = 0; p < 3; p++) {
            int nb0 = nw + p * 16;
            bAddr[p] = (uint32_t)__cvta_generic_to_shared(
                Bs + (nb0 + bRow) * B_STR + bCol);
        }

        #pragma unroll
        for (int kk = 0; kk < 32; kk += 16) {
            uint32_t a[2][4];
            ldsm4(a[0], aAddr[0] + kk * 2);
            ldsm4(a[1], aAddr[1] + kk * 2);
            #pragma unroll
            for (int p = 0; p < 3; p++) {
                uint32_t bb[4];
                ldsm4(bb, bAddr[p] + kk * 2);
                mma16(c[0][2 * p],     a[0], bb[0], bb[1]);
                mma16(c[1][2 * p],     a[1], bb[0], bb[1]);
                mma16(c[0][2 * p + 1], a[0], bb[2], bb[3]);
                mma16(c[1][2 * p + 1], a[1], bb[2], bb[3]);
            }
        }

        if (it + 2 < NSTG) fetchB(it + 2);
    }

    #pragma unroll
    for (int mt = 0; mt < 2; mt++) {
        int rbase = m0 + mw + mt * 16 + g;
        #pragma unroll
        for (int half = 0; half < 2; half++) {
            int r = rbase + half * 8;
            if (r < NN) {
                float s = ds[(size_t)f * NN + r];
                __half* dst = g_Th + (size_t)r * FT + f * FOUT + nw;
                #pragma unroll
                for (int nt = 0; nt < 6; nt++) {
                    __half2 p = __floats2half2_rn(s * c[mt][nt][half * 2 + 0],
                                                  s * c[mt][nt][half * 2 + 1]);
                    *(__half2*)(dst + nt * 8 + 2 * t4) = p;
                }
            }
        }
    }
}

// ---------------------------------------------------------------------------
// Fused SPMM + diag + relu + scale + bias + out (R10 verbatim, unroll-4)
// ---------------------------------------------------------------------------
__device__ __forceinline__ void fmah(float4& acc, float a, uint2 q) {
    float2 lo = __half22float2(*(const __half2*)&q.x);
    float2 hi = __half22float2(*(const __half2*)&q.y);
    acc.x = fmaf(a, lo.x, acc.x);
    acc.y = fmaf(a, lo.y, acc.y);
    acc.z = fmaf(a, hi.x, acc.z);
    acc.w = fmaf(a, hi.y, acc.w);
}

__device__ __forceinline__ float4 relu4(float4 v) {
    return make_float4(fmaxf(v.x, 0.f), fmaxf(v.y, 0.f),
                       fmaxf(v.z, 0.f), fmaxf(v.w, 0.f));
}

__device__ __forceinline__ float4 fma4(float a, float4 v, float4 c) {
    c.x = fmaf(a, v.x, c.x);
    c.y = fmaf(a, v.y, c.y);
    c.z = fmaf(a, v.z, c.z);
    c.w = fmaf(a, v.w, c.w);
    return c;
}

__global__ __launch_bounds__(256) void k_spmm(const float* __restrict__ ds,
                                              const float* __restrict__ bias,
                                              float* __restrict__ out) {
    int r = blockIdx.x * 8 + (threadIdx.x >> 5);
    int l = threadIdx.x & 31;
    if (r >= NN) return;

    const int2* bucket = g_csrb + (size_t)r * CAP;
    int truecnt = g_cnt[r];
    int cnt = truecnt < CAP ? truecnt : CAP;
    int n1 = cnt < 32 ? cnt : 32;

    int2 hdr = bucket[l];
    const bool act = (l < 24);

    float4 a0 = make_float4(0.f, 0.f, 0.f, 0.f);
    float4 a1 = a0, a2 = a0;

    int e = 0;
    for (; e + 3 < n1; e += 4) {
        int   c0 = __shfl_sync(0xffffffffu, hdr.x, e);
        int   c1 = __shfl_sync(0xffffffffu, hdr.x, e + 1);
        int   c2 = __shfl_sync(0xffffffffu, hdr.x, e + 2);
        int   c3 = __shfl_sync(0xffffffffu, hdr.x, e + 3);
        float v0 = __int_as_float(__shfl_sync(0xffffffffu, hdr.y, e));
        float v1 = __int_as_float(__shfl_sync(0xffffffffu, hdr.y, e + 1));
        float v2 = __int_as_float(__shfl_sync(0xffffffffu, hdr.y, e + 2));
        float v3 = __int_as_float(__shfl_sync(0xffffffffu, hdr.y, e + 3));
        if (act) {
            const uint2* p0 = (const uint2*)(g_Th + (size_t)c0 * FT);
            const uint2* p1 = (const uint2*)(g_Th + (size_t)c1 * FT);
            const uint2* p2 = (const uint2*)(g_Th + (size_t)c2 * FT);
            const uint2* p3 = (const uint2*)(g_Th + (size_t)c3 * FT);
            uint2 x0 = p0[l], x1 = p0[l + 24], x2 = p0[l + 48];
            uint2 y0 = p1[l], y1 = p1[l + 24], y2 = p1[l + 48];
            uint2 z0 = p2[l], z1 = p2[l + 24], z2 = p2[l + 48];
            uint2 w0 = p3[l], w1 = p3[l + 24], w2 = p3[l + 48];
            fmah(a0, v0, x0); fmah(a1, v0, x1); fmah(a2, v0, x2);
            fmah(a0, v1, y0); fmah(a1, v1, y1); fmah(a2, v1, y2);
            fmah(a0, v2, z0); fmah(a1, v2, z1); fmah(a2, v2, z2);
            fmah(a0, v3, w0); fmah(a1, v3, w1); fmah(a2, v3, w2);
        }
    }
    for (; e < n1; e++) {
        int   c0 = __shfl_sync(0xffffffffu, hdr.x, e);
        float v0 = __int_as_float(__shfl_sync(0xffffffffu, hdr.y, e));
        if (act) {
            const uint2* p = (const uint2*)(g_Th + (size_t)c0 * FT);
            fmah(a0, v0, p[l]);
            fmah(a1, v0, p[l + 24]);
            fmah(a2, v0, p[l + 48]);
        }
    }
    for (; e < cnt; e++) {
        int2 h = bucket[e];
        if (act) {
            float v = __int_as_float(h.y);
            const uint2* p = (const uint2*)(g_Th + (size_t)h.x * FT);
            fmah(a0, v, p[l]);
            fmah(a1, v, p[l + 24]);
            fmah(a2, v, p[l + 48]);
        }
    }

    if (!act) return;

    float k = EPS / ((float)truecnt + 1.0f);
    const uint2* pr = (const uint2*)(g_Th + (size_t)r * FT);
    fmah(a0, -k, pr[l]);
    fmah(a1,  k, pr[l + 24]);
    fmah(a2,  k, pr[l + 48]);

    float d0 = ds[r];
    float d1 = ds[NN + r];
    float d2 = ds[2 * NN + r];
    float4 o = ((const float4*)bias)[l];
    o = fma4(d0, relu4(a0), o);
    o = fma4(d1, relu4(a1), o);
    o = fma4(d2, relu4(a2), o);
    ((float4*)out)[(size_t)r * 24 + l] = o;
}

// ---------------------------------------------------------------------------
extern "C" void kernel_launch(void* const* d_in, const int* in_sizes, int n_in,
                              void* d_out, int out_size) {
    const float* x    = (const float*)d_in[0];  // [N, 256]
    const float* adj  = (const float*)d_in[1];  // [E]
    const float* ds   = (const float*)d_in[2];  // [3, N]
    const float* w    = (const float*)d_in[3];  // [3, 256, 96]
    const float* bias = (const float*)d_in[4];  // [96]
    const int*   ei   = (const int*)d_in[5];    // [2, E]
    float* out = (float*)d_out;                 // [N, 96]

    static cudaStream_t s2 = nullptr;
    static cudaEvent_t evFork = nullptr, evJoin = nullptr;
    if (!s2) {
        cudaStreamCreateWithFlags(&s2, cudaStreamNonBlocking);
        cudaEventCreateWithFlags(&evFork, cudaEventDisableTiming);
        cudaEventCreateWithFlags(&evJoin, cudaEventDisableTiming);
        cudaFuncSetAttribute(k_gemm, cudaFuncAttributeMaxDynamicSharedMemorySize,
                             GEMM_SMEM);
    }

    // s2: CSR build (gates spmm); main: wcvt -> gemm -> spmm
    cudaEventRecord(evFork, 0);
    cudaStreamWaitEvent(s2, evFork, 0);

    k_cnt0<<<(NN + 255) / 256, 256, 0, s2>>>();
    k_bucket<<<(EE + 255) / 256, 256, 0, s2>>>(ei, adj);
    cudaEventRecord(evJoin, s2);

    k_wcvt<<<(NF * FIN * FOUT + 255) / 256, 256>>>(w);
    k_gemm<<<dim3((NN + 127) / 128, NF), 256, GEMM_SMEM>>>(ds, x);
    cudaStreamWaitEvent(0, evJoin, 0);
    k_spmm<<<(NN + 7) / 8, 256>>>(ds, bias, out);
}